// round 1
// baseline (speedup 1.0000x reference)
#include <cuda_runtime.h>
#include <cstdint>

// Problem constants
#define BB 32
#define SS 2048
#define HH 32
#define NOPE 128
#define VD 128
#define HID 4096
#define QKVN 12288              // 4096 q (compact nope) + 4096 k + 4096 v
#define SCALE 0.08838834764831843f   // 128^-0.5

#define NCHUNK 4
#define CHUNK 512

// ---------------- scratch (static device globals; no runtime alloc) -------------
__device__ float g_p1[4u * 32u * 12288u];        // GEMM1 split-K partials (6 MB)
__device__ float g_qkv[32u * 12288u];            // fused q/k/v projections
__device__ float g_pm[1024 * NCHUNK];            // per-(b,h,chunk) running max
__device__ float g_pl[1024 * NCHUNK];            // per-(b,h,chunk) exp-sum
__device__ float g_pacc[1024 * NCHUNK * 128];    // per-chunk weighted V (2 MB)
__device__ float g_attn[32u * 4096u];            // attention output [B][H*VD]
__device__ float g_p2[8u * 32u * 4096u];         // GEMM2 split-K partials (4 MB)

// packed f32x2 fma (Blackwell sm_100+); doubles fp32 FMA throughput
__device__ __forceinline__ unsigned long long ffma2(unsigned long long a,
                                                    unsigned long long b,
                                                    unsigned long long c) {
    unsigned long long d;
    asm("fma.rn.f32x2 %0, %1, %2, %3;" : "=l"(d) : "l"(a), "l"(b), "l"(c));
    return d;
}

// =====================================================================
// GEMM: C[32][N] = A[32][4096] @ W[N][4096]^T, split-K partials.
// MODE 0: fused QKV. Virtual col n: n<4096 -> Wq row (n>>7)*192 + (n&127)
//         (skips unused rope rows); n>=4096 -> Wkv row n-4096 (k then v,
//         contiguous in Wkv; rope tail rows 8192..8255 skipped entirely).
//         A = hidden_states param, partials -> g_p1.
// MODE 1: plain W0 = Wo, A = g_attn, partials -> g_p2.
// Block: 128 threads, tile BM=32 x BN=256 x BK=32, thread tile 8x8,
// A duplicated pairwise in smem so ulonglong2 loads feed f32x2 FMAs directly.
// =====================================================================
template <int MODE>
__global__ void __launch_bounds__(128) gemm_kernel(const float* __restrict__ A,
                                                   const float* __restrict__ W0,
                                                   const float* __restrict__ W1,
                                                   int N, int ksteps) {
    __shared__ __align__(16) float As[32][64];    // [kk][2*m] duplicated
    __shared__ __align__(16) float Ws[32][256];   // [kk][n]

    const int t = threadIdx.x;
    const int n0 = blockIdx.x * 256;
    const int kbase = blockIdx.y * (ksteps * 32);

    const float* Ap = (MODE == 0) ? A : g_attn;
    float* part = (MODE == 0) ? g_p1 : g_p2;

    // W row pointers for the 16 load passes (16 rows per pass, 8 thr/row)
    const float* wrow[16];
#pragma unroll
    for (int p = 0; p < 16; p++) {
        int n = n0 + (t >> 3) + p * 16;
        if (MODE == 0) {
            wrow[p] = (n < 4096)
                          ? (W0 + (size_t)((n >> 7) * 192 + (n & 127)) * HID)
                          : (W1 + (size_t)(n - 4096) * HID);
        } else {
            wrow[p] = W0 + (size_t)n * HID;
        }
    }
    const int c4 = (t & 7) * 4;
    const int mrow = (t >> 3);
    const float* arow0 = Ap + (size_t)mrow * HID;
    const float* arow1 = Ap + (size_t)(mrow + 16) * HID;

    unsigned long long acc[8][4];
#pragma unroll
    for (int i = 0; i < 8; i++)
#pragma unroll
        for (int j = 0; j < 4; j++) acc[i][j] = 0ull;

    const int tmb = (t >> 5) * 8;   // 8 M-rows per thread
    const int tnb = (t & 31) * 8;   // 8 N-cols per thread

    for (int ks = 0; ks < ksteps; ks++) {
        const int k = kbase + ks * 32 + c4;
        float4 va = *(const float4*)(arow0 + k);
        float4 vb = *(const float4*)(arow1 + k);
#pragma unroll
        for (int i = 0; i < 4; i++) {
            float v0 = (&va.x)[i];
            As[c4 + i][2 * mrow] = v0;
            As[c4 + i][2 * mrow + 1] = v0;
            float v1 = (&vb.x)[i];
            As[c4 + i][2 * (mrow + 16)] = v1;
            As[c4 + i][2 * (mrow + 16) + 1] = v1;
        }
#pragma unroll
        for (int p = 0; p < 16; p++) {
            float4 v = *(const float4*)(wrow[p] + k);
            int nl = (t >> 3) + p * 16;
#pragma unroll
            for (int i = 0; i < 4; i++) Ws[c4 + i][nl] = (&v.x)[i];
        }
        __syncthreads();
#pragma unroll
        for (int kk = 0; kk < 32; kk++) {
            const ulonglong2* ap = (const ulonglong2*)&As[kk][2 * tmb];
            const ulonglong2* bp = (const ulonglong2*)&Ws[kk][tnb];
            ulonglong2 A0 = ap[0], A1 = ap[1], A2 = ap[2], A3 = ap[3];
            ulonglong2 B0 = bp[0], B1 = bp[1];
            unsigned long long av[8] = {A0.x, A0.y, A1.x, A1.y,
                                        A2.x, A2.y, A3.x, A3.y};
            unsigned long long bv[4] = {B0.x, B0.y, B1.x, B1.y};
#pragma unroll
            for (int i = 0; i < 8; i++)
#pragma unroll
                for (int j = 0; j < 4; j++)
                    acc[i][j] = ffma2(av[i], bv[j], acc[i][j]);
        }
        __syncthreads();
    }
#pragma unroll
    for (int i = 0; i < 8; i++) {
        float* prow = part + ((size_t)blockIdx.y * 32 + tmb + i) * N + n0 + tnb;
#pragma unroll
        for (int j = 0; j < 4; j++) {
            prow[2 * j] = __uint_as_float((unsigned)(acc[i][j] & 0xffffffffull));
            prow[2 * j + 1] = __uint_as_float((unsigned)(acc[i][j] >> 32));
        }
    }
}

// sum the 4 GEMM1 split-K partials -> g_qkv
__global__ void reduce_qkv_kernel() {
    int i = blockIdx.x * 256 + threadIdx.x;   // 393216 total
    g_qkv[i] = g_p1[i] + g_p1[i + 393216] + g_p1[i + 2 * 393216] +
               g_p1[i + 3 * 393216];
}

// =====================================================================
// Flash-decoding attention partial: one block per (b,h,chunk of 512).
// Phase 1: 8 warps compute scores (2 tokens/iter for MLP), store to smem.
// Phase 2: block softmax over the chunk. Phase 3: weighted V accumulation
// (128 dims x 2 s-halves). The token at s==pos uses the freshly projected
// k/v from g_qkv instead of the (unmodified) paged cache.
// =====================================================================
__global__ void __launch_bounds__(256) attn_partial_kernel(
    const float* __restrict__ k_cache, const float* __restrict__ v_cache,
    const int* __restrict__ positions) {
    const int bh = blockIdx.x;
    const int c = blockIdx.y;
    const int b = bh >> 5, h = bh & 31;
    const int t = threadIdx.x, lane = t & 31, w = t >> 5;
    const int pos = positions[b];
    const int L = pos + 1;
    const int s0 = c * CHUNK;
    const int len = min(CHUNK, L - s0);
    const int pidx = bh * NCHUNK + c;
    if (len <= 0) {
        if (t == 0) { g_pl[pidx] = 0.f; g_pm[pidx] = -1e30f; }
        return;
    }

    __shared__ float sc[CHUNK];
    __shared__ float red[256];
    __shared__ float redw[8];
    __shared__ float s_m, s_l;

    const float* qb = g_qkv + b * QKVN + h * 128;
    const float4 q4 = *(const float4*)(qb + lane * 4);
    const float* knew = g_qkv + b * QKVN + 4096 + h * 128;
    const float* kbasep = k_cache + (size_t)b * SS * (HH * 128) + h * 128;

    for (int sl = 2 * w; sl < len; sl += 16) {
        int s1 = s0 + sl;
        const float* k1 = (s1 == pos) ? knew : (kbasep + (size_t)s1 * 4096);
        int sl2 = sl + 1;
        bool two = (sl2 < len);
        int s2 = s0 + sl2;
        const float* k2 =
            two ? ((s2 == pos) ? knew : (kbasep + (size_t)s2 * 4096)) : k1;
        float4 ka = *(const float4*)(k1 + lane * 4);
        float4 kb = *(const float4*)(k2 + lane * 4);
        float da = ka.x * q4.x + ka.y * q4.y + ka.z * q4.z + ka.w * q4.w;
        float db = kb.x * q4.x + kb.y * q4.y + kb.z * q4.z + kb.w * q4.w;
#pragma unroll
        for (int o = 16; o; o >>= 1) {
            da += __shfl_xor_sync(0xffffffffu, da, o);
            db += __shfl_xor_sync(0xffffffffu, db, o);
        }
        if (lane == 0) {
            sc[sl] = da * SCALE;
            if (two) sc[sl2] = db * SCALE;
        }
    }
    __syncthreads();

    // ---- softmax over the chunk ----
    float lm = -1e30f;
    if (t < len) lm = sc[t];
    if (t + 256 < len) lm = fmaxf(lm, sc[t + 256]);
#pragma unroll
    for (int o = 16; o; o >>= 1) lm = fmaxf(lm, __shfl_xor_sync(0xffffffffu, lm, o));
    if (lane == 0) redw[w] = lm;
    __syncthreads();
    if (t == 0) {
        float m = redw[0];
#pragma unroll
        for (int i = 1; i < 8; i++) m = fmaxf(m, redw[i]);
        s_m = m;
    }
    __syncthreads();
    const float m = s_m;
    float ls = 0.f;
    if (t < len) {
        float p = __expf(sc[t] - m);
        sc[t] = p;
        ls += p;
    }
    if (t + 256 < len) {
        float p = __expf(sc[t + 256] - m);
        sc[t + 256] = p;
        ls += p;
    }
#pragma unroll
    for (int o = 16; o; o >>= 1) ls += __shfl_xor_sync(0xffffffffu, ls, o);
    if (lane == 0) redw[w] = ls;
    __syncthreads();
    if (t == 0) {
        float l = 0.f;
#pragma unroll
        for (int i = 0; i < 8; i++) l += redw[i];
        s_l = l;
    }
    __syncthreads();

    // ---- weighted V accumulation ----
    const float* vnew = g_qkv + b * QKVN + 8192 + h * 128;
    const float* vbasep = v_cache + (size_t)b * SS * (HH * 128) + h * 128;
    const int d = t & 127;
    const int half = t >> 7;
    float acc = 0.f;
#pragma unroll 4
    for (int sl = half; sl < len; sl += 2) {
        int s = s0 + sl;
        const float* vr = (s == pos) ? vnew : (vbasep + (size_t)s * 4096);
        acc += sc[sl] * vr[d];
    }
    red[t] = acc;
    __syncthreads();
    if (t < 128) g_pacc[(size_t)pidx * 128 + t] = red[t] + red[t + 128];
    if (t == 0) {
        g_pm[pidx] = m;
        g_pl[pidx] = s_l;
    }
}

// combine the <=4 chunk partials per (b,h) -> g_attn[b][h*VD+d]
__global__ void __launch_bounds__(128) attn_combine_kernel() {
    const int bh = blockIdx.x;
    const int d = threadIdx.x;
    float M = -1e30f;
#pragma unroll
    for (int c = 0; c < NCHUNK; c++) {
        float l = g_pl[bh * NCHUNK + c];
        if (l > 0.f) M = fmaxf(M, g_pm[bh * NCHUNK + c]);
    }
    float L = 0.f, o = 0.f;
#pragma unroll
    for (int c = 0; c < NCHUNK; c++) {
        float l = g_pl[bh * NCHUNK + c];
        if (l > 0.f) {
            float wgt = __expf(g_pm[bh * NCHUNK + c] - M);
            L += l * wgt;
            o += g_pacc[(size_t)(bh * NCHUNK + c) * 128 + d] * wgt;
        }
    }
    const int b = bh >> 5, h = bh & 31;
    g_attn[b * 4096 + h * 128 + d] = o / L;
}

// sum the 8 GEMM2 split-K partials -> final output
__global__ void reduce_out_kernel(float* __restrict__ out) {
    int i = blockIdx.x * 256 + threadIdx.x;   // 131072 total
    float s = 0.f;
#pragma unroll
    for (int c = 0; c < 8; c++) s += g_p2[i + c * 131072];
    out[i] = s;
}

extern "C" void kernel_launch(void* const* d_in, const int* in_sizes, int n_in,
                              void* d_out, int out_size) {
    const float* hs = (const float*)d_in[0];
    const int* positions = (const int*)d_in[1];
    const float* k_cache = (const float*)d_in[2];
    const float* v_cache = (const float*)d_in[3];
    const float* Wq = (const float*)d_in[4];
    const float* Wkv = (const float*)d_in[5];
    const float* Wo = (const float*)d_in[6];
    float* out = (float*)d_out;

    // 1) fused q(nope)/k/v projection, split-K=4 (48 N-tiles x 4 = 192 blocks)
    gemm_kernel<0><<<dim3(48, 4), 128>>>(hs, Wq, Wkv, QKVN, 32);
    reduce_qkv_kernel<<<1536, 256>>>();
    // 2) flash-decoding attention partials (32*32 pairs x 4 chunks)
    attn_partial_kernel<<<dim3(1024, NCHUNK), 256>>>(k_cache, v_cache, positions);
    attn_combine_kernel<<<1024, 128>>>();
    // 3) output projection, split-K=8 (16 N-tiles x 8 = 128 blocks)
    gemm_kernel<1><<<dim3(16, 8), 128>>>(nullptr, Wo, nullptr, HID, 16);
    reduce_out_kernel<<<512, 256>>>(out);
}

// round 2
// speedup vs baseline: 1.2503x; 1.2503x over previous
#include <cuda_runtime.h>
#include <cstdint>

// Problem constants
#define BB 32
#define SS 2048
#define HH 32
#define NOPE 128
#define VD 128
#define HID 4096
#define QKVN 12288              // 4096 q (compact nope) + 4096 k + 4096 v
#define SCALE 0.08838834764831843f   // 128^-0.5

#define NCHUNK 8
#define CHUNK 256

// ---------------- scratch (static device globals; no runtime alloc) -------------
__device__ float g_p1[8u * 32u * 12288u];        // GEMM1 split-K partials (12 MB)
__device__ float g_qkv[32u * 12288u];            // fused q/k/v projections
__device__ float g_pm[1024 * NCHUNK];            // per-(b,h,chunk) running max
__device__ float g_pl[1024 * NCHUNK];            // per-(b,h,chunk) exp-sum
__device__ float g_pacc[1024 * NCHUNK * 128];    // per-chunk weighted V (4 MB)
__device__ float g_attn[32u * 4096u];            // attention output [B][H*VD]
__device__ float g_p2[8u * 32u * 4096u];         // GEMM2 split-K partials (4 MB)

// packed f32x2 fma (Blackwell sm_100+); doubles fp32 FMA throughput
__device__ __forceinline__ unsigned long long ffma2(unsigned long long a,
                                                    unsigned long long b,
                                                    unsigned long long c) {
    unsigned long long d;
    asm("fma.rn.f32x2 %0, %1, %2, %3;" : "=l"(d) : "l"(a), "l"(b), "l"(c));
    return d;
}

// =====================================================================
// GEMM: C[32][N] = A[32][4096] @ W[N][4096]^T, split-K partials.
// MODE 0: fused QKV (virtual col mapping skips unused rope rows).
// MODE 1: plain Wo, A = g_attn.
// BN = 256 or 128. 128 threads, BM=32 x BN x BK=32, thread tile 8 x (BN/32),
// A duplicated pairwise in smem so ulonglong2 loads feed f32x2 FMAs directly.
// =====================================================================
template <int MODE, int BN>
__global__ void __launch_bounds__(128) gemm_kernel(const float* __restrict__ A,
                                                   const float* __restrict__ W0,
                                                   const float* __restrict__ W1,
                                                   int N, int ksteps) {
    constexpr int NPASS = BN / 16;   // W-load passes
    constexpr int NP2 = BN / 64;     // u64 accumulators per M-row

    __shared__ __align__(16) float As[32][64];    // [kk][2*m] duplicated
    __shared__ __align__(16) float Ws[32][BN];    // [kk][n]

    const int t = threadIdx.x;
    const int n0 = blockIdx.x * BN;
    const int kbase = blockIdx.y * (ksteps * 32);

    const float* Ap = (MODE == 0) ? A : g_attn;
    float* part = (MODE == 0) ? g_p1 : g_p2;

    const float* wrow[NPASS];
#pragma unroll
    for (int p = 0; p < NPASS; p++) {
        int n = n0 + (t >> 3) + p * 16;
        if (MODE == 0) {
            wrow[p] = (n < 4096)
                          ? (W0 + (size_t)((n >> 7) * 192 + (n & 127)) * HID)
                          : (W1 + (size_t)(n - 4096) * HID);
        } else {
            wrow[p] = W0 + (size_t)n * HID;
        }
    }
    const int c4 = (t & 7) * 4;
    const int mrow = (t >> 3);
    const float* arow0 = Ap + (size_t)mrow * HID;
    const float* arow1 = Ap + (size_t)(mrow + 16) * HID;

    unsigned long long acc[8][NP2];
#pragma unroll
    for (int i = 0; i < 8; i++)
#pragma unroll
        for (int j = 0; j < NP2; j++) acc[i][j] = 0ull;

    const int tmb = (t >> 5) * 8;           // 8 M-rows per thread
    const int tnb = (t & 31) * (BN / 32);   // BN/32 N-cols per thread

    for (int ks = 0; ks < ksteps; ks++) {
        const int k = kbase + ks * 32 + c4;
        float4 va = *(const float4*)(arow0 + k);
        float4 vb = *(const float4*)(arow1 + k);
#pragma unroll
        for (int i = 0; i < 4; i++) {
            float v0 = (&va.x)[i];
            As[c4 + i][2 * mrow] = v0;
            As[c4 + i][2 * mrow + 1] = v0;
            float v1 = (&vb.x)[i];
            As[c4 + i][2 * (mrow + 16)] = v1;
            As[c4 + i][2 * (mrow + 16) + 1] = v1;
        }
#pragma unroll
        for (int p = 0; p < NPASS; p++) {
            float4 v = *(const float4*)(wrow[p] + k);
            int nl = (t >> 3) + p * 16;
#pragma unroll
            for (int i = 0; i < 4; i++) Ws[c4 + i][nl] = (&v.x)[i];
        }
        __syncthreads();
#pragma unroll
        for (int kk = 0; kk < 32; kk++) {
            const ulonglong2* ap = (const ulonglong2*)&As[kk][2 * tmb];
            const ulonglong2* bp = (const ulonglong2*)&Ws[kk][tnb];
            ulonglong2 A0 = ap[0], A1 = ap[1], A2 = ap[2], A3 = ap[3];
            unsigned long long av[8] = {A0.x, A0.y, A1.x, A1.y,
                                        A2.x, A2.y, A3.x, A3.y};
            unsigned long long bv[NP2];
#pragma unroll
            for (int j = 0; j < NP2 / 2; j++) {
                ulonglong2 B = bp[j];
                bv[2 * j] = B.x;
                bv[2 * j + 1] = B.y;
            }
#pragma unroll
            for (int i = 0; i < 8; i++)
#pragma unroll
                for (int j = 0; j < NP2; j++)
                    acc[i][j] = ffma2(av[i], bv[j], acc[i][j]);
        }
        __syncthreads();
    }
#pragma unroll
    for (int i = 0; i < 8; i++) {
        float* prow = part + ((size_t)blockIdx.y * 32 + tmb + i) * N + n0 + tnb;
#pragma unroll
        for (int j = 0; j < NP2; j++) {
            prow[2 * j] = __uint_as_float((unsigned)(acc[i][j] & 0xffffffffull));
            prow[2 * j + 1] = __uint_as_float((unsigned)(acc[i][j] >> 32));
        }
    }
}

// sum the 8 GEMM1 split-K partials -> g_qkv
__global__ void reduce_qkv_kernel() {
    int i = blockIdx.x * 256 + threadIdx.x;   // 393216 total
    float s = 0.f;
#pragma unroll
    for (int c = 0; c < 8; c++) s += g_p1[i + c * 393216];
    g_qkv[i] = s;
}

// =====================================================================
// Flash-decoding attention partial: one block per (b,h,chunk of 256).
// Phase 1: 8 warps compute scores, 4 tokens/warp-iter (MLP=4, interleaved
// shfl butterflies). Phase 2: single-pass block softmax (256 thr = CHUNK).
// Phase 3: weighted V accumulation. Token s==pos substitutes the freshly
// projected k/v from g_qkv (caches are never mutated).
// =====================================================================
__global__ void __launch_bounds__(256) attn_partial_kernel(
    const float* __restrict__ k_cache, const float* __restrict__ v_cache,
    const int* __restrict__ positions) {
    const int bh = blockIdx.x;
    const int c = blockIdx.y;
    const int b = bh >> 5, h = bh & 31;
    const int t = threadIdx.x, lane = t & 31, w = t >> 5;
    const int pos = positions[b];
    const int L = pos + 1;
    const int s0 = c * CHUNK;
    const int len = min(CHUNK, L - s0);
    const int pidx = bh * NCHUNK + c;
    if (len <= 0) {
        if (t == 0) { g_pl[pidx] = 0.f; g_pm[pidx] = -1e30f; }
        return;
    }

    __shared__ float sc[CHUNK];
    __shared__ float red[256];
    __shared__ float redw[8];
    __shared__ float s_m, s_l;

    const float* qb = g_qkv + b * QKVN + h * 128;
    const float4 q4 = *(const float4*)(qb + lane * 4);
    const float* knew = g_qkv + b * QKVN + 4096 + h * 128;
    const float* kbasep = k_cache + (size_t)b * SS * (HH * 128) + h * 128;

    for (int sl = 4 * w; sl < len; sl += 32) {
        float4 kv[4];
        float dd[4];
#pragma unroll
        for (int i = 0; i < 4; i++) {
            int sli = sl + i;
            int s = s0 + sli;
            const float* kp = (sli < len)
                                  ? ((s == pos) ? knew
                                                : (kbasep + (size_t)s * 4096))
                                  : knew;   // safe dummy
            kv[i] = *(const float4*)(kp + lane * 4);
        }
#pragma unroll
        for (int i = 0; i < 4; i++)
            dd[i] = kv[i].x * q4.x + kv[i].y * q4.y + kv[i].z * q4.z +
                    kv[i].w * q4.w;
#pragma unroll
        for (int o = 16; o; o >>= 1) {
#pragma unroll
            for (int i = 0; i < 4; i++)
                dd[i] += __shfl_xor_sync(0xffffffffu, dd[i], o);
        }
        if (lane == 0) {
#pragma unroll
            for (int i = 0; i < 4; i++)
                if (sl + i < len) sc[sl + i] = dd[i] * SCALE;
        }
    }
    __syncthreads();

    // ---- softmax over the chunk (256 threads cover CHUNK=256) ----
    float lm = (t < len) ? sc[t] : -1e30f;
#pragma unroll
    for (int o = 16; o; o >>= 1) lm = fmaxf(lm, __shfl_xor_sync(0xffffffffu, lm, o));
    if (lane == 0) redw[w] = lm;
    __syncthreads();
    if (t == 0) {
        float m = redw[0];
#pragma unroll
        for (int i = 1; i < 8; i++) m = fmaxf(m, redw[i]);
        s_m = m;
    }
    __syncthreads();
    const float m = s_m;
    float ls = 0.f;
    if (t < len) {
        float p = __expf(sc[t] - m);
        sc[t] = p;
        ls = p;
    }
#pragma unroll
    for (int o = 16; o; o >>= 1) ls += __shfl_xor_sync(0xffffffffu, ls, o);
    if (lane == 0) redw[w] = ls;
    __syncthreads();
    if (t == 0) {
        float l = 0.f;
#pragma unroll
        for (int i = 0; i < 8; i++) l += redw[i];
        s_l = l;
    }
    __syncthreads();

    // ---- weighted V accumulation ----
    const float* vnew = g_qkv + b * QKVN + 8192 + h * 128;
    const float* vbasep = v_cache + (size_t)b * SS * (HH * 128) + h * 128;
    const int d = t & 127;
    const int half = t >> 7;
    float acc = 0.f;
#pragma unroll 8
    for (int sl = half; sl < len; sl += 2) {
        int s = s0 + sl;
        const float* vr = (s == pos) ? vnew : (vbasep + (size_t)s * 4096);
        acc += sc[sl] * vr[d];
    }
    red[t] = acc;
    __syncthreads();
    if (t < 128) g_pacc[(size_t)pidx * 128 + t] = red[t] + red[t + 128];
    if (t == 0) {
        g_pm[pidx] = m;
        g_pl[pidx] = s_l;
    }
}

// combine the <=8 chunk partials per (b,h) -> g_attn[b][h*VD+d]
__global__ void __launch_bounds__(128) attn_combine_kernel() {
    const int bh = blockIdx.x;
    const int d = threadIdx.x;
    float M = -1e30f;
#pragma unroll
    for (int c = 0; c < NCHUNK; c++) {
        float l = g_pl[bh * NCHUNK + c];
        if (l > 0.f) M = fmaxf(M, g_pm[bh * NCHUNK + c]);
    }
    float L = 0.f, o = 0.f;
#pragma unroll
    for (int c = 0; c < NCHUNK; c++) {
        float l = g_pl[bh * NCHUNK + c];
        if (l > 0.f) {
            float wgt = __expf(g_pm[bh * NCHUNK + c] - M);
            L += l * wgt;
            o += g_pacc[(size_t)(bh * NCHUNK + c) * 128 + d] * wgt;
        }
    }
    const int b = bh >> 5, h = bh & 31;
    g_attn[b * 4096 + h * 128 + d] = o / L;
}

// sum the 8 GEMM2 split-K partials -> final output
__global__ void reduce_out_kernel(float* __restrict__ out) {
    int i = blockIdx.x * 256 + threadIdx.x;   // 131072 total
    float s = 0.f;
#pragma unroll
    for (int c = 0; c < 8; c++) s += g_p2[i + c * 131072];
    out[i] = s;
}

extern "C" void kernel_launch(void* const* d_in, const int* in_sizes, int n_in,
                              void* d_out, int out_size) {
    const float* hs = (const float*)d_in[0];
    const int* positions = (const int*)d_in[1];
    const float* k_cache = (const float*)d_in[2];
    const float* v_cache = (const float*)d_in[3];
    const float* Wq = (const float*)d_in[4];
    const float* Wkv = (const float*)d_in[5];
    const float* Wo = (const float*)d_in[6];
    float* out = (float*)d_out;

    // 1) fused q(nope)/k/v projection, split-K=8 (48 N-tiles x 8 = 384 blocks)
    gemm_kernel<0, 256><<<dim3(48, 8), 128>>>(hs, Wq, Wkv, QKVN, 16);
    reduce_qkv_kernel<<<1536, 256>>>();
    // 2) flash-decoding attention partials (1024 bh-pairs x 8 chunks of 256)
    attn_partial_kernel<<<dim3(1024, NCHUNK), 256>>>(k_cache, v_cache, positions);
    attn_combine_kernel<<<1024, 128>>>();
    // 3) output projection BN=128, split-K=8 (32 N-tiles x 8 = 256 blocks)
    gemm_kernel<1, 128><<<dim3(32, 8), 128>>>(nullptr, Wo, nullptr, HID, 16);
    reduce_out_kernel<<<512, 256>>>(out);
}